// round 1
// baseline (speedup 1.0000x reference)
#include <cuda_runtime.h>
#include <math.h>

#define B_ 8
#define N_ 1024
#define C_ 768
#define H_ 12
#define D_ 64
#define M_ (B_*N_)   // 8192

// Scratch (allocation-free rule: __device__ globals)
__device__ float g_q[B_*H_*N_*D_];    // [B,H,N,D]
__device__ float g_k[B_*H_*N_*D_];
__device__ float g_v[B_*H_*N_*D_];
__device__ float g_att[M_*C_];        // [B,N,C] attention output

// ---------------------------------------------------------------------------
// Tiled SGEMM: Cout = A[M,768] @ Bw[768,LDB] (+bias).
// 128x128 block tile, BK=8, 256 threads, 8x8 microtile (split 4+4).
// QKV=true: scatter into g_q/g_k/g_v with bias. QKV=false: A:=g_att, write Out.
// ---------------------------------------------------------------------------
template<int LDB, bool QKV>
__global__ __launch_bounds__(256) void gemm_kernel(
    const float* __restrict__ A, const float* __restrict__ Bw,
    const float* __restrict__ bias, float* __restrict__ Out)
{
  __shared__ float As[8][128];
  __shared__ float Bs[8][128];
  const int tid = threadIdx.x;
  const int tx = tid & 15, ty = tid >> 4;
  const int m0 = blockIdx.y * 128, n0 = blockIdx.x * 128;

  const float* Ap = QKV ? A : g_att;

  const int arow = tid >> 1;          // 0..127
  const int acol = (tid & 1) << 2;    // 0 or 4
  const int brow = tid >> 5;          // 0..7
  const int bcol = (tid & 31) << 2;   // 0..124

  const float* aptr = Ap + (size_t)(m0 + arow) * 768 + acol;
  const float* bptr = Bw + (size_t)brow * LDB + n0 + bcol;

  float acc[8][8];
#pragma unroll
  for (int i = 0; i < 8; i++)
#pragma unroll
    for (int j = 0; j < 8; j++) acc[i][j] = 0.f;

  float4 av = *(const float4*)aptr;
  float4 bv = *(const float4*)bptr;

  for (int kt = 0; kt < 96; kt++) {
    As[acol+0][arow] = av.x;
    As[acol+1][arow] = av.y;
    As[acol+2][arow] = av.z;
    As[acol+3][arow] = av.w;
    *(float4*)&Bs[brow][bcol] = bv;
    __syncthreads();
    if (kt < 95) {   // prefetch next tile while computing this one
      av = *(const float4*)(aptr + (kt+1)*8);
      bv = *(const float4*)(bptr + (size_t)(kt+1)*8*LDB);
    }
#pragma unroll
    for (int k = 0; k < 8; k++) {
      float a[8], b[8];
      *(float4*)&a[0] = *(float4*)&As[k][ty*4];
      *(float4*)&a[4] = *(float4*)&As[k][64 + ty*4];
      *(float4*)&b[0] = *(float4*)&Bs[k][tx*4];
      *(float4*)&b[4] = *(float4*)&Bs[k][64 + tx*4];
#pragma unroll
      for (int i = 0; i < 8; i++)
#pragma unroll
        for (int j = 0; j < 8; j++)
          acc[i][j] += a[i]*b[j];
    }
    __syncthreads();
  }

  int rows[8], cols[8];
#pragma unroll
  for (int i = 0; i < 4; i++) {
    rows[i]   = m0 + ty*4 + i;  rows[i+4] = m0 + 64 + ty*4 + i;
    cols[i]   = n0 + tx*4 + i;  cols[i+4] = n0 + 64 + tx*4 + i;
  }

  if (QKV) {
#pragma unroll
    for (int i = 0; i < 8; i++) {
      const int gr = rows[i];
      const int bb = gr >> 10, t = gr & 1023;
#pragma unroll
      for (int j = 0; j < 8; j++) {
        const int gc = cols[j];
        const int which = gc / 768;
        const int c = gc - which*768;
        const int hh = c >> 6, d = c & 63;
        const float v = acc[i][j] + bias[gc];
        float* dst = (which == 0) ? g_q : (which == 1) ? g_k : g_v;
        dst[(((size_t)(bb*12 + hh) << 10) + t)*64 + d] = v;
      }
    }
  } else {
#pragma unroll
    for (int i = 0; i < 8; i++) {
      const int gr = rows[i];
#pragma unroll
      for (int jg = 0; jg < 2; jg++) {
        float4 o;
        o.x = acc[i][jg*4+0] + bias[cols[jg*4+0]];
        o.y = acc[i][jg*4+1] + bias[cols[jg*4+1]];
        o.z = acc[i][jg*4+2] + bias[cols[jg*4+2]];
        o.w = acc[i][jg*4+3] + bias[cols[jg*4+3]];
        *(float4*)&Out[(size_t)gr*768 + cols[jg*4]] = o;
      }
    }
  }
}

// ---------------------------------------------------------------------------
// Flash-attention-style fused kernel.
// Block: one (b,h) x 64-row Q tile. 256 threads (16x16 logical).
// Per thread: S micro-tile rows ty*4+i (q), cols j*16+tx (k);
//             O micro-tile rows ty*4+i (q), cols tx*4+j (d).
// Ks is XOR-swizzled (float4 granularity) for conflict-free column reads;
// Ps aliases the Ks buffer (K is dead after S) -> exactly 48KB static smem.
// ---------------------------------------------------------------------------
__global__ __launch_bounds__(256) void attn_kernel(const int* __restrict__ pad_mask)
{
  __shared__ float Qs[64*64];
  __shared__ float Vs[64*64];
  __shared__ float Ks[64*64];   // swizzled; re-used as Ps after S-phase

  const int tid = threadIdx.x;
  const int tx = tid & 15, ty = tid >> 4;
  const int bh = blockIdx.y;
  const int b  = bh / 12;
  const int q0 = blockIdx.x << 6;

  const float* Qg = g_q + (size_t)bh * (N_*D_) + (size_t)q0 * D_;
  const float* Kg = g_k + (size_t)bh * (N_*D_);
  const float* Vg = g_v + (size_t)bh * (N_*D_);

  for (int idx = tid; idx < 64*16; idx += 256) {
    const int r = idx >> 4, c4 = (idx & 15) << 2;
    *(float4*)&Qs[r*64 + c4] = *(const float4*)&Qg[r*64 + c4];
  }

  bool mz[4];
#pragma unroll
  for (int i = 0; i < 4; i++)
    mz[i] = (pad_mask[b*N_ + q0 + ty*4 + i] == 0);

  float accO[4][4];
  float rowM[4], rowL[4];
#pragma unroll
  for (int i = 0; i < 4; i++) {
    rowM[i] = -INFINITY; rowL[i] = 0.f;
#pragma unroll
    for (int j = 0; j < 4; j++) accO[i][j] = 0.f;
  }

  for (int kt = 0; kt < 16; kt++) {
    const float* Kt = Kg + (size_t)(kt << 6) * 64;
    const float* Vt = Vg + (size_t)(kt << 6) * 64;
    for (int idx = tid; idx < 64*16; idx += 256) {
      const int r = idx >> 4, c4 = idx & 15;
      *(float4*)&Ks[r*64 + ((c4 ^ (r & 15)) << 2)] = *(const float4*)&Kt[r*64 + (c4 << 2)];
      *(float4*)&Vs[r*64 + (c4 << 2)]              = *(const float4*)&Vt[r*64 + (c4 << 2)];
    }
    __syncthreads();

    // S = Q K^T  (per-thread 4x4, vectorized over d)
    float s[4][4];
#pragma unroll
    for (int i = 0; i < 4; i++)
#pragma unroll
      for (int j = 0; j < 4; j++) s[i][j] = 0.f;

#pragma unroll
    for (int d4 = 0; d4 < 16; d4++) {
      float4 qa[4], kb[4];
#pragma unroll
      for (int i = 0; i < 4; i++)
        qa[i] = *(float4*)&Qs[(ty*4 + i)*64 + (d4 << 2)];
#pragma unroll
      for (int j = 0; j < 4; j++) {
        const int kr = j*16 + tx;
        kb[j] = *(float4*)&Ks[kr*64 + ((d4 ^ (kr & 15)) << 2)];
      }
#pragma unroll
      for (int i = 0; i < 4; i++)
#pragma unroll
        for (int j = 0; j < 4; j++)
          s[i][j] += qa[i].x*kb[j].x + qa[i].y*kb[j].y + qa[i].z*kb[j].z + qa[i].w*kb[j].w;
    }

    // online softmax (row stats reduced across the 16 tx lanes)
    float p[4][4];
#pragma unroll
    for (int i = 0; i < 4; i++) {
      float m = -INFINITY;
#pragma unroll
      for (int j = 0; j < 4; j++) {
        s[i][j] = mz[i] ? -INFINITY : s[i][j] * 0.125f;
        m = fmaxf(m, s[i][j]);
      }
#pragma unroll
      for (int o = 8; o; o >>= 1)
        m = fmaxf(m, __shfl_xor_sync(0xffffffffu, m, o));
      const float mnew = fmaxf(rowM[i], m);
      const float fac  = __expf(rowM[i] - mnew);
      rowM[i] = mnew;
      float ps = 0.f;
#pragma unroll
      for (int j = 0; j < 4; j++) {
        p[i][j] = __expf(s[i][j] - mnew);
        ps += p[i][j];
      }
#pragma unroll
      for (int o = 8; o; o >>= 1)
        ps += __shfl_xor_sync(0xffffffffu, ps, o);
      rowL[i] = rowL[i]*fac + ps;
#pragma unroll
      for (int j = 0; j < 4; j++) accO[i][j] *= fac;
    }

    __syncthreads();            // everyone done reading Ks
    float* Ps = Ks;             // alias: P overwrites K tile
#pragma unroll
    for (int i = 0; i < 4; i++)
#pragma unroll
      for (int j = 0; j < 4; j++)
        Ps[(ty*4 + i)*64 + j*16 + tx] = p[i][j];
    __syncthreads();

    // O += P V
#pragma unroll
    for (int k4 = 0; k4 < 16; k4++) {
      float4 pa[4];
#pragma unroll
      for (int i = 0; i < 4; i++)
        pa[i] = *(float4*)&Ps[(ty*4 + i)*64 + (k4 << 2)];
      const float4 v0 = *(float4*)&Vs[(k4*4 + 0)*64 + (tx << 2)];
      const float4 v1 = *(float4*)&Vs[(k4*4 + 1)*64 + (tx << 2)];
      const float4 v2 = *(float4*)&Vs[(k4*4 + 2)*64 + (tx << 2)];
      const float4 v3 = *(float4*)&Vs[(k4*4 + 3)*64 + (tx << 2)];
#pragma unroll
      for (int i = 0; i < 4; i++) {
        accO[i][0] += pa[i].x*v0.x + pa[i].y*v1.x + pa[i].z*v2.x + pa[i].w*v3.x;
        accO[i][1] += pa[i].x*v0.y + pa[i].y*v1.y + pa[i].z*v2.y + pa[i].w*v3.y;
        accO[i][2] += pa[i].x*v0.z + pa[i].y*v1.z + pa[i].z*v2.z + pa[i].w*v3.z;
        accO[i][3] += pa[i].x*v0.w + pa[i].y*v1.w + pa[i].z*v2.w + pa[i].w*v3.w;
      }
    }
    __syncthreads();
  }

  const int h = bh % 12;
#pragma unroll
  for (int i = 0; i < 4; i++) {
    const float inv = 1.f / rowL[i];
    float4 o;
    o.x = accO[i][0]*inv; o.y = accO[i][1]*inv;
    o.z = accO[i][2]*inv; o.w = accO[i][3]*inv;
    *(float4*)&g_att[(size_t)(b*N_ + q0 + ty*4 + i)*C_ + h*64 + (tx << 2)] = o;
  }
}

extern "C" void kernel_launch(void* const* d_in, const int* in_sizes, int n_in,
                              void* d_out, int out_size) {
  const float* x      = (const float*)d_in[0];
  const int*   pad    = (const int*)  d_in[1];
  const float* w_attn = (const float*)d_in[2];
  const float* b_attn = (const float*)d_in[3];
  const float* w_proj = (const float*)d_in[4];
  const float* b_proj = (const float*)d_in[5];
  float* out = (float*)d_out;

  // 1) QKV projection + bias + scatter to [B,H,N,D]
  gemm_kernel<2304, true><<<dim3(18, 64), 256>>>(x, w_attn, b_attn, nullptr);
  // 2) fused attention (softmax with pad mask over query rows)
  attn_kernel<<<dim3(16, 96), 256>>>(pad);
  // 3) output projection + bias -> d_out
  gemm_kernel<768, false><<<dim3(6, 64), 256>>>(nullptr, w_proj, b_proj, out);
}

// round 4
// speedup vs baseline: 1.1189x; 1.1189x over previous
#include <cuda_runtime.h>
#include <math.h>
#include <stdint.h>

#define B_ 8
#define N_ 1024
#define C_ 768
#define H_ 12
#define D_ 64
#define M_ (B_*N_)   // 8192

// Scratch (allocation-free rule: __device__ globals)
__device__ float g_q[B_*H_*N_*D_];    // [B,H,N,D]
__device__ float g_k[B_*H_*N_*D_];
__device__ float g_v[B_*H_*N_*D_];
__device__ float g_att[M_*C_];        // [B,N,C] attention output

// ---------------------------------------------------------------------------
// mma.sync tf32 helpers (sm_80+ PTX — works on the compute_103 base target)
// ---------------------------------------------------------------------------
__device__ __forceinline__ uint32_t f2tf32(float f) {
  uint32_t u;
  asm("cvt.rna.tf32.f32 %0, %1;" : "=r"(u) : "f"(f));
  return u;
}

__device__ __forceinline__ void mma_tf32(float* d, const uint32_t* a, const uint32_t* b) {
  asm volatile(
    "mma.sync.aligned.m16n8k8.row.col.f32.tf32.tf32.f32 "
    "{%0,%1,%2,%3}, {%4,%5,%6,%7}, {%8,%9}, {%0,%1,%2,%3};"
    : "+f"(d[0]), "+f"(d[1]), "+f"(d[2]), "+f"(d[3])
    : "r"(a[0]), "r"(a[1]), "r"(a[2]), "r"(a[3]), "r"(b[0]), "r"(b[1]));
}

// ---------------------------------------------------------------------------
// tf32 tensor-core GEMM: Out[m][n] = sum_k A[m][k] * W[k][n] (+bias)
// CTA 128x128, 256 threads = 8 warps (4m x 2n), warp tile 32x64.
// K staged 16 per iteration; smem in fragment-contiguous layout:
//   A: [kc(2)][mfrag(8)][lane(32)][slot(4)]  (LDS.128 per frag, conflict-free)
//   B: [kc(2)][nfrag(16)][lane(32)][slot(2)] (LDS.64 per frag, conflict-free)
// Fragment layouts per PTX m16n8k8 tf32:
//   A slot: 0=(r,c) 1=(r+8,c) 2=(r,c+4) 3=(r+8,c+4), lane=(r&7)*4+(c&3)
//   B slot: 0=k<4 1=k>=4,                  lane=(n&7)*4+(k&3)
//   C regs: 0,1 = (g, 2t),(g, 2t+1); 2,3 = (g+8, ...)  g=lane>>2, t=lane&3
// QKV=true: A = x, W = w_attn[768][2304], scatter into g_q/g_k/g_v.
// QKV=false: A = g_att, W = w_proj[768][768], write Out.
// ---------------------------------------------------------------------------
template<int LDN, bool QKV>
__global__ __launch_bounds__(256) void mma_gemm(
    const float* __restrict__ Ain, const float* __restrict__ W,
    const float* __restrict__ bias, float* __restrict__ Out)
{
  __shared__ uint32_t As[2048];   // 8KB
  __shared__ uint32_t Bs[2048];   // 8KB

  const int tid  = threadIdx.x;
  const int lane = tid & 31;
  const int w    = tid >> 5;
  const int wm   = w & 3;          // warp m index (0..3)
  const int wn   = w >> 2;         // warp n index (0..1)
  const int m0 = blockIdx.y * 128, n0 = blockIdx.x * 128;

  const float* A = QKV ? Ain : g_att;

  float acc[2][8][4];
#pragma unroll
  for (int i = 0; i < 2; i++)
#pragma unroll
    for (int j = 0; j < 8; j++)
#pragma unroll
      for (int q = 0; q < 4; q++) acc[i][j][q] = 0.f;

  // --- per-thread staging coordinates (2 iters each for A and B) ---
  // A: idx = tid + it*256 in 0..511 ; row = idx>>2 (0..127), k4 = idx&3
  int a_row[2], a_k4[2], a_base[2];
  // B: idx = tid + it*256 ; n = idx&127, k4 = idx>>7 (0..3)
  int b_n[2], b_k4[2], b_base[2];
#pragma unroll
  for (int it = 0; it < 2; it++) {
    const int ia = tid + it * 256;
    a_row[it] = ia >> 2;
    a_k4[it]  = ia & 3;
    {
      const int row = a_row[it], k4 = a_k4[it];
      const int kc = k4 >> 1;
      const int slot = ((row >> 3) & 1) | ((k4 & 1) << 1);
      const int mf = row >> 4;
      a_base[it] = (kc * 8 + mf) * 128 + (row & 7) * 16 + slot;
    }
    const int ib = tid + it * 256;
    b_n[it]  = ib & 127;
    b_k4[it] = ib >> 7;
    {
      const int n = b_n[it], k4 = b_k4[it];
      const int kc = k4 >> 1;
      const int nf = n >> 3;
      const int slot = k4 & 1;
      b_base[it] = (kc * 16 + nf) * 64 + (n & 7) * 8 + slot;
    }
  }

  float4 pa[2];
  float  pb[8];

  // prefetch stage 0
#pragma unroll
  for (int it = 0; it < 2; it++) {
    pa[it] = *(const float4*)&A[(size_t)(m0 + a_row[it]) * 768 + a_k4[it] * 4];
#pragma unroll
    for (int i = 0; i < 4; i++)
      pb[it * 4 + i] = W[(size_t)(b_k4[it] * 4 + i) * LDN + n0 + b_n[it]];
  }

  for (int kt = 0; kt < 48; kt++) {
    // store prefetched stage into smem (tf32-converted, permuted layout)
#pragma unroll
    for (int it = 0; it < 2; it++) {
      As[a_base[it] + 0]  = f2tf32(pa[it].x);
      As[a_base[it] + 4]  = f2tf32(pa[it].y);
      As[a_base[it] + 8]  = f2tf32(pa[it].z);
      As[a_base[it] + 12] = f2tf32(pa[it].w);
      Bs[b_base[it] + 0]  = f2tf32(pb[it * 4 + 0]);
      Bs[b_base[it] + 2]  = f2tf32(pb[it * 4 + 1]);
      Bs[b_base[it] + 4]  = f2tf32(pb[it * 4 + 2]);
      Bs[b_base[it] + 6]  = f2tf32(pb[it * 4 + 3]);
    }
    __syncthreads();

    if (kt < 47) {
      const int k0 = (kt + 1) * 16;
#pragma unroll
      for (int it = 0; it < 2; it++) {
        pa[it] = *(const float4*)&A[(size_t)(m0 + a_row[it]) * 768 + k0 + a_k4[it] * 4];
#pragma unroll
        for (int i = 0; i < 4; i++)
          pb[it * 4 + i] = W[(size_t)(k0 + b_k4[it] * 4 + i) * LDN + n0 + b_n[it]];
      }
    }

    // compute: 2 k-chunks of 8
#pragma unroll
    for (int kc = 0; kc < 2; kc++) {
      uint32_t af[2][4];
#pragma unroll
      for (int mf2 = 0; mf2 < 2; mf2++) {
        const uint32_t* p = &As[(kc * 8 + wm * 2 + mf2) * 128 + lane * 4];
        const uint4 v = *(const uint4*)p;
        af[mf2][0] = v.x; af[mf2][1] = v.y; af[mf2][2] = v.z; af[mf2][3] = v.w;
      }
#pragma unroll
      for (int nf = 0; nf < 8; nf++) {
        uint32_t bf[2];
        const uint32_t* p = &Bs[(kc * 16 + wn * 8 + nf) * 64 + lane * 2];
        bf[0] = p[0]; bf[1] = p[1];
        mma_tf32(acc[0][nf], af[0], bf);
        mma_tf32(acc[1][nf], af[1], bf);
      }
    }
    __syncthreads();
  }

  // --- epilogue: bias + store (float2 per C reg-pair) ---
  const int g = lane >> 2, tq = lane & 3;
#pragma unroll
  for (int mf2 = 0; mf2 < 2; mf2++) {
    const int r0 = m0 + wm * 32 + mf2 * 16 + g;
#pragma unroll
    for (int nf = 0; nf < 8; nf++) {
      const int col = n0 + wn * 64 + nf * 8 + tq * 2;
      const float bx = bias[col], by = bias[col + 1];
#pragma unroll
      for (int half = 0; half < 2; half++) {
        const int r = r0 + half * 8;
        float2 o;
        o.x = acc[mf2][nf][half * 2 + 0] + bx;
        o.y = acc[mf2][nf][half * 2 + 1] + by;
        if (QKV) {
          const int bb = r >> 10, t = r & 1023;
          const int which = col / 768;
          const int c = col - which * 768;
          const int hh = c >> 6, d = c & 63;
          float* dst = (which == 0) ? g_q : (which == 1) ? g_k : g_v;
          *(float2*)&dst[((size_t)((bb * 12 + hh) * 1024 + t)) * 64 + d] = o;
        } else {
          *(float2*)&Out[(size_t)r * 768 + col] = o;
        }
      }
    }
  }
}

// ---------------------------------------------------------------------------
// Flash-attention-style fused kernel (unchanged, fp32 SIMT, proven correct).
// ---------------------------------------------------------------------------
__global__ __launch_bounds__(256) void attn_kernel(const int* __restrict__ pad_mask)
{
  __shared__ float Qs[64*64];
  __shared__ float Vs[64*64];
  __shared__ float Ks[64*64];   // swizzled; re-used as Ps after S-phase

  const int tid = threadIdx.x;
  const int tx = tid & 15, ty = tid >> 4;
  const int bh = blockIdx.y;
  const int b  = bh / 12;
  const int q0 = blockIdx.x << 6;

  const float* Qg = g_q + (size_t)bh * (N_*D_) + (size_t)q0 * D_;
  const float* Kg = g_k + (size_t)bh * (N_*D_);
  const float* Vg = g_v + (size_t)bh * (N_*D_);

  for (int idx = tid; idx < 64*16; idx += 256) {
    const int r = idx >> 4, c4 = (idx & 15) << 2;
    *(float4*)&Qs[r*64 + c4] = *(const float4*)&Qg[r*64 + c4];
  }

  bool mz[4];
#pragma unroll
  for (int i = 0; i < 4; i++)
    mz[i] = (pad_mask[b*N_ + q0 + ty*4 + i] == 0);

  float accO[4][4];
  float rowM[4], rowL[4];
#pragma unroll
  for (int i = 0; i < 4; i++) {
    rowM[i] = -INFINITY; rowL[i] = 0.f;
#pragma unroll
    for (int j = 0; j < 4; j++) accO[i][j] = 0.f;
  }

  for (int kt = 0; kt < 16; kt++) {
    const float* Kt = Kg + (size_t)(kt << 6) * 64;
    const float* Vt = Vg + (size_t)(kt << 6) * 64;
    for (int idx = tid; idx < 64*16; idx += 256) {
      const int r = idx >> 4, c4 = idx & 15;
      *(float4*)&Ks[r*64 + ((c4 ^ (r & 15)) << 2)] = *(const float4*)&Kt[r*64 + (c4 << 2)];
      *(float4*)&Vs[r*64 + (c4 << 2)]              = *(const float4*)&Vt[r*64 + (c4 << 2)];
    }
    __syncthreads();

    float s[4][4];
#pragma unroll
    for (int i = 0; i < 4; i++)
#pragma unroll
      for (int j = 0; j < 4; j++) s[i][j] = 0.f;

#pragma unroll
    for (int d4 = 0; d4 < 16; d4++) {
      float4 qa[4], kb[4];
#pragma unroll
      for (int i = 0; i < 4; i++)
        qa[i] = *(float4*)&Qs[(ty*4 + i)*64 + (d4 << 2)];
#pragma unroll
      for (int j = 0; j < 4; j++) {
        const int kr = j*16 + tx;
        kb[j] = *(float4*)&Ks[kr*64 + ((d4 ^ (kr & 15)) << 2)];
      }
#pragma unroll
      for (int i = 0; i < 4; i++)
#pragma unroll
        for (int j = 0; j < 4; j++)
          s[i][j] += qa[i].x*kb[j].x + qa[i].y*kb[j].y + qa[i].z*kb[j].z + qa[i].w*kb[j].w;
    }

    float p[4][4];
#pragma unroll
    for (int i = 0; i < 4; i++) {
      float m = -INFINITY;
#pragma unroll
      for (int j = 0; j < 4; j++) {
        s[i][j] = mz[i] ? -INFINITY : s[i][j] * 0.125f;
        m = fmaxf(m, s[i][j]);
      }
#pragma unroll
      for (int o = 8; o; o >>= 1)
        m = fmaxf(m, __shfl_xor_sync(0xffffffffu, m, o));
      const float mnew = fmaxf(rowM[i], m);
      const float fac  = __expf(rowM[i] - mnew);
      rowM[i] = mnew;
      float ps = 0.f;
#pragma unroll
      for (int j = 0; j < 4; j++) {
        p[i][j] = __expf(s[i][j] - mnew);
        ps += p[i][j];
      }
#pragma unroll
      for (int o = 8; o; o >>= 1)
        ps += __shfl_xor_sync(0xffffffffu, ps, o);
      rowL[i] = rowL[i]*fac + ps;
#pragma unroll
      for (int j = 0; j < 4; j++) accO[i][j] *= fac;
    }

    __syncthreads();
    float* Ps = Ks;
#pragma unroll
    for (int i = 0; i < 4; i++)
#pragma unroll
      for (int j = 0; j < 4; j++)
        Ps[(ty*4 + i)*64 + j*16 + tx] = p[i][j];
    __syncthreads();

#pragma unroll
    for (int k4 = 0; k4 < 16; k4++) {
      float4 pa[4];
#pragma unroll
      for (int i = 0; i < 4; i++)
        pa[i] = *(float4*)&Ps[(ty*4 + i)*64 + (k4 << 2)];
      const float4 v0 = *(float4*)&Vs[(k4*4 + 0)*64 + (tx << 2)];
      const float4 v1 = *(float4*)&Vs[(k4*4 + 1)*64 + (tx << 2)];
      const float4 v2 = *(float4*)&Vs[(k4*4 + 2)*64 + (tx << 2)];
      const float4 v3 = *(float4*)&Vs[(k4*4 + 3)*64 + (tx << 2)];
#pragma unroll
      for (int i = 0; i < 4; i++) {
        accO[i][0] += pa[i].x*v0.x + pa[i].y*v1.x + pa[i].z*v2.x + pa[i].w*v3.x;
        accO[i][1] += pa[i].x*v0.y + pa[i].y*v1.y + pa[i].z*v2.y + pa[i].w*v3.y;
        accO[i][2] += pa[i].x*v0.z + pa[i].y*v1.z + pa[i].z*v2.z + pa[i].w*v3.z;
        accO[i][3] += pa[i].x*v0.w + pa[i].y*v1.w + pa[i].z*v2.w + pa[i].w*v3.w;
      }
    }
    __syncthreads();
  }

  const int h = bh % 12;
#pragma unroll
  for (int i = 0; i < 4; i++) {
    const float inv = 1.f / rowL[i];
    float4 o;
    o.x = accO[i][0]*inv; o.y = accO[i][1]*inv;
    o.z = accO[i][2]*inv; o.w = accO[i][3]*inv;
    *(float4*)&g_att[(size_t)(b*N_ + q0 + ty*4 + i)*C_ + h*64 + (tx << 2)] = o;
  }
}

extern "C" void kernel_launch(void* const* d_in, const int* in_sizes, int n_in,
                              void* d_out, int out_size) {
  const float* x      = (const float*)d_in[0];
  const int*   pad    = (const int*)  d_in[1];
  const float* w_attn = (const float*)d_in[2];
  const float* b_attn = (const float*)d_in[3];
  const float* w_proj = (const float*)d_in[4];
  const float* b_proj = (const float*)d_in[5];
  float* out = (float*)d_out;

  // 1) QKV projection (mma.sync tf32) + bias + scatter to [B,H,N,D]
  mma_gemm<2304, true><<<dim3(18, 64), 256>>>(x, w_attn, b_attn, nullptr);
  // 2) fused attention (fp32 SIMT, pad mask over query rows)
  attn_kernel<<<dim3(16, 96), 256>>>(pad);
  // 3) output projection (mma.sync tf32) + bias -> d_out
  mma_gemm<768, false><<<dim3(6, 64), 256>>>(nullptr, w_proj, b_proj, out);
}

// round 5
// speedup vs baseline: 1.5635x; 1.3974x over previous
#include <cuda_runtime.h>
#include <math.h>
#include <stdint.h>

#define B_ 8
#define N_ 1024
#define C_ 768
#define H_ 12
#define D_ 64
#define M_ (B_*N_)   // 8192

// Scratch (allocation-free rule: __device__ globals)
__device__ float g_q[B_*H_*N_*D_];    // [B,H,N,D]
__device__ float g_k[B_*H_*N_*D_];
__device__ float g_v[B_*H_*N_*D_];
__device__ float g_att[M_*C_];        // [B,N,C] attention output

// ---------------------------------------------------------------------------
// mma.sync tf32 helpers (sm_80+ PTX — works on the compute_103 base target)
// ---------------------------------------------------------------------------
__device__ __forceinline__ uint32_t f2tf32(float f) {
  uint32_t u;
  asm("cvt.rna.tf32.f32 %0, %1;" : "=r"(u) : "f"(f));
  return u;
}

__device__ __forceinline__ void mma_tf32(float* d, const uint32_t* a, const uint32_t* b) {
  asm volatile(
    "mma.sync.aligned.m16n8k8.row.col.f32.tf32.tf32.f32 "
    "{%0,%1,%2,%3}, {%4,%5,%6,%7}, {%8,%9}, {%0,%1,%2,%3};"
    : "+f"(d[0]), "+f"(d[1]), "+f"(d[2]), "+f"(d[3])
    : "r"(a[0]), "r"(a[1]), "r"(a[2]), "r"(a[3]), "r"(b[0]), "r"(b[1]));
}

// ---------------------------------------------------------------------------
// tf32 tensor-core GEMM (unchanged from R4, proven): Out = A @ W (+bias)
// ---------------------------------------------------------------------------
template<int LDN, bool QKV>
__global__ __launch_bounds__(256) void mma_gemm(
    const float* __restrict__ Ain, const float* __restrict__ W,
    const float* __restrict__ bias, float* __restrict__ Out)
{
  __shared__ uint32_t As[2048];   // 8KB
  __shared__ uint32_t Bs[2048];   // 8KB

  const int tid  = threadIdx.x;
  const int lane = tid & 31;
  const int w    = tid >> 5;
  const int wm   = w & 3;
  const int wn   = w >> 2;
  const int m0 = blockIdx.y * 128, n0 = blockIdx.x * 128;

  const float* A = QKV ? Ain : g_att;

  float acc[2][8][4];
#pragma unroll
  for (int i = 0; i < 2; i++)
#pragma unroll
    for (int j = 0; j < 8; j++)
#pragma unroll
      for (int q = 0; q < 4; q++) acc[i][j][q] = 0.f;

  int a_row[2], a_k4[2], a_base[2];
  int b_n[2], b_k4[2], b_base[2];
#pragma unroll
  for (int it = 0; it < 2; it++) {
    const int ia = tid + it * 256;
    a_row[it] = ia >> 2;
    a_k4[it]  = ia & 3;
    {
      const int row = a_row[it], k4 = a_k4[it];
      const int kc = k4 >> 1;
      const int slot = ((row >> 3) & 1) | ((k4 & 1) << 1);
      const int mf = row >> 4;
      a_base[it] = (kc * 8 + mf) * 128 + (row & 7) * 16 + slot;
    }
    const int ib = tid + it * 256;
    b_n[it]  = ib & 127;
    b_k4[it] = ib >> 7;
    {
      const int n = b_n[it], k4 = b_k4[it];
      const int kc = k4 >> 1;
      const int nf = n >> 3;
      const int slot = k4 & 1;
      b_base[it] = (kc * 16 + nf) * 64 + (n & 7) * 8 + slot;
    }
  }

  float4 pa[2];
  float  pb[8];

#pragma unroll
  for (int it = 0; it < 2; it++) {
    pa[it] = *(const float4*)&A[(size_t)(m0 + a_row[it]) * 768 + a_k4[it] * 4];
#pragma unroll
    for (int i = 0; i < 4; i++)
      pb[it * 4 + i] = W[(size_t)(b_k4[it] * 4 + i) * LDN + n0 + b_n[it]];
  }

  for (int kt = 0; kt < 48; kt++) {
#pragma unroll
    for (int it = 0; it < 2; it++) {
      As[a_base[it] + 0]  = f2tf32(pa[it].x);
      As[a_base[it] + 4]  = f2tf32(pa[it].y);
      As[a_base[it] + 8]  = f2tf32(pa[it].z);
      As[a_base[it] + 12] = f2tf32(pa[it].w);
      Bs[b_base[it] + 0]  = f2tf32(pb[it * 4 + 0]);
      Bs[b_base[it] + 2]  = f2tf32(pb[it * 4 + 1]);
      Bs[b_base[it] + 4]  = f2tf32(pb[it * 4 + 2]);
      Bs[b_base[it] + 6]  = f2tf32(pb[it * 4 + 3]);
    }
    __syncthreads();

    if (kt < 47) {
      const int k0 = (kt + 1) * 16;
#pragma unroll
      for (int it = 0; it < 2; it++) {
        pa[it] = *(const float4*)&A[(size_t)(m0 + a_row[it]) * 768 + k0 + a_k4[it] * 4];
#pragma unroll
        for (int i = 0; i < 4; i++)
          pb[it * 4 + i] = W[(size_t)(k0 + b_k4[it] * 4 + i) * LDN + n0 + b_n[it]];
      }
    }

#pragma unroll
    for (int kc = 0; kc < 2; kc++) {
      uint32_t af[2][4];
#pragma unroll
      for (int mf2 = 0; mf2 < 2; mf2++) {
        const uint32_t* p = &As[(kc * 8 + wm * 2 + mf2) * 128 + lane * 4];
        const uint4 v = *(const uint4*)p;
        af[mf2][0] = v.x; af[mf2][1] = v.y; af[mf2][2] = v.z; af[mf2][3] = v.w;
      }
#pragma unroll
      for (int nf = 0; nf < 8; nf++) {
        uint32_t bf[2];
        const uint32_t* p = &Bs[(kc * 16 + wn * 8 + nf) * 64 + lane * 2];
        bf[0] = p[0]; bf[1] = p[1];
        mma_tf32(acc[0][nf], af[0], bf);
        mma_tf32(acc[1][nf], af[1], bf);
      }
    }
    __syncthreads();
  }

  const int g = lane >> 2, tq = lane & 3;
#pragma unroll
  for (int mf2 = 0; mf2 < 2; mf2++) {
    const int r0 = m0 + wm * 32 + mf2 * 16 + g;
#pragma unroll
    for (int nf = 0; nf < 8; nf++) {
      const int col = n0 + wn * 64 + nf * 8 + tq * 2;
      const float bx = bias[col], by = bias[col + 1];
#pragma unroll
      for (int half = 0; half < 2; half++) {
        const int r = r0 + half * 8;
        float2 o;
        o.x = acc[mf2][nf][half * 2 + 0] + bx;
        o.y = acc[mf2][nf][half * 2 + 1] + by;
        if (QKV) {
          const int bb = r >> 10, t = r & 1023;
          const int which = col / 768;
          const int c = col - which * 768;
          const int hh = c >> 6, d = c & 63;
          float* dst = (which == 0) ? g_q : (which == 1) ? g_k : g_v;
          *(float2*)&dst[((size_t)((bb * 12 + hh) * 1024 + t)) * 64 + d] = o;
        } else {
          *(float2*)&Out[(size_t)r * 768 + col] = o;
        }
      }
    }
  }
}

// ---------------------------------------------------------------------------
// Tensor-core flash attention (tf32 mma.sync).
// CTA: 128 Q-rows of one (b,h); 256 threads = 8 warps; warp w owns rows
// [16w,16w+16) -> softmax is warp-local (reduce over the 4 t-lanes).
// Smem (dynamic 64KB):
//   QPs[8192]: Q in A-frag layout [kc(8)][mf(8)][128]; after Q is hoisted to
//              registers the same region holds P (warp-private slices).
//   Ks[4096]:  K tile (64 keys) in B-frag layout, k=d, n=key.
//   Vs[4096]:  V tile in B-frag layout, k=key, n=d.
// Fragment index math identical to mma_gemm (validated in R4).
// ---------------------------------------------------------------------------
__global__ __launch_bounds__(256) void attn_mma(const int* __restrict__ pad_mask)
{
  extern __shared__ uint32_t smem[];
  uint32_t* QPs = smem;            // 32KB
  uint32_t* Ks  = smem + 8192;     // 16KB
  uint32_t* Vs  = smem + 12288;    // 16KB

  const int tid  = threadIdx.x;
  const int lane = tid & 31;
  const int w    = tid >> 5;
  const int g    = lane >> 2;      // row within 8-group
  const int t    = lane & 3;       // col group
  const int bh = blockIdx.y;
  const int b  = bh / 12, h = bh % 12;
  const int q0 = blockIdx.x << 7;  // 128 Q rows per CTA

  const float* Qg = g_q + (size_t)bh * (N_*D_) + (size_t)q0 * D_;
  const float* Kg = g_k + (size_t)bh * (N_*D_);
  const float* Vg = g_v + (size_t)bh * (N_*D_);

  // --- stage Q (128x64) into A-frag layout ---
#pragma unroll
  for (int it = 0; it < 8; it++) {
    const int idx = tid + it * 256;      // 0..2047
    const int r = idx >> 4, d4 = idx & 15;
    const float4 qv = *(const float4*)&Qg[(size_t)r * 64 + d4 * 4];
    const int base = ((d4 >> 1) * 8 + (r >> 4)) * 128 + (r & 7) * 16
                   + (d4 & 1) * 2 + ((r >> 3) & 1);
    QPs[base + 0]  = f2tf32(qv.x);
    QPs[base + 4]  = f2tf32(qv.y);
    QPs[base + 8]  = f2tf32(qv.z);
    QPs[base + 12] = f2tf32(qv.w);
  }
  __syncthreads();

  // hoist Q fragments: warp w reads only its mf=w slices
  uint32_t aQ[8][4];
#pragma unroll
  for (int kc = 0; kc < 8; kc++) {
    const uint4 v = *(const uint4*)&QPs[(kc * 8 + w) * 128 + lane * 4];
    aQ[kc][0] = v.x; aQ[kc][1] = v.y; aQ[kc][2] = v.z; aQ[kc][3] = v.w;
  }

  const bool mz0 = (pad_mask[b * N_ + q0 + w * 16 + g] == 0);
  const bool mz1 = (pad_mask[b * N_ + q0 + w * 16 + g + 8] == 0);

  float accO[8][4];
#pragma unroll
  for (int nf = 0; nf < 8; nf++)
#pragma unroll
    for (int j = 0; j < 4; j++) accO[nf][j] = 0.f;
  float rowM0 = -INFINITY, rowM1 = -INFINITY, rowL0 = 0.f, rowL1 = 0.f;

  for (int kt = 0; kt < 16; kt++) {
    __syncthreads();   // previous iteration's Ks/Vs reads done
    // --- stage K and V tiles (64 keys x 64 d each) ---
#pragma unroll
    for (int it = 0; it < 4; it++) {
      const int idx = tid + it * 256;    // 0..1023
      const int r = idx >> 4, d4 = idx & 15;
      const float4 kv = *(const float4*)&Kg[(size_t)(kt * 64 + r) * 64 + d4 * 4];
      const int kb = ((d4 >> 1) * 8 + (r >> 3)) * 64 + (r & 7) * 8 + (d4 & 1);
      Ks[kb + 0] = f2tf32(kv.x);
      Ks[kb + 2] = f2tf32(kv.y);
      Ks[kb + 4] = f2tf32(kv.z);
      Ks[kb + 6] = f2tf32(kv.w);
      const float4 vv = *(const float4*)&Vg[(size_t)(kt * 64 + r) * 64 + d4 * 4];
      const int vb = ((r >> 3) * 8 + (d4 >> 1)) * 64 + (d4 & 1) * 32
                   + (r & 3) * 2 + ((r >> 2) & 1);
      Vs[vb + 0]  = f2tf32(vv.x);
      Vs[vb + 8]  = f2tf32(vv.y);
      Vs[vb + 16] = f2tf32(vv.z);
      Vs[vb + 24] = f2tf32(vv.w);
    }
    __syncthreads();

    // --- S = Q K^T : per warp 16x64, 8kc x 8nf mma ---
    float accS[8][4];
#pragma unroll
    for (int nf = 0; nf < 8; nf++)
#pragma unroll
      for (int j = 0; j < 4; j++) accS[nf][j] = 0.f;
#pragma unroll
    for (int kc = 0; kc < 8; kc++) {
#pragma unroll
      for (int nf = 0; nf < 8; nf++) {
        uint32_t bf[2];
        const uint32_t* p = &Ks[(kc * 8 + nf) * 64 + lane * 2];
        bf[0] = p[0]; bf[1] = p[1];
        mma_tf32(accS[nf], aQ[kc], bf);
      }
    }

    // --- online softmax (warp-local; rows g and g+8) ---
    float mx0 = -INFINITY, mx1 = -INFINITY;
#pragma unroll
    for (int nf = 0; nf < 8; nf++) {
      accS[nf][0] = mz0 ? -INFINITY : accS[nf][0] * 0.125f;
      accS[nf][1] = mz0 ? -INFINITY : accS[nf][1] * 0.125f;
      accS[nf][2] = mz1 ? -INFINITY : accS[nf][2] * 0.125f;
      accS[nf][3] = mz1 ? -INFINITY : accS[nf][3] * 0.125f;
      mx0 = fmaxf(mx0, fmaxf(accS[nf][0], accS[nf][1]));
      mx1 = fmaxf(mx1, fmaxf(accS[nf][2], accS[nf][3]));
    }
#pragma unroll
    for (int o = 1; o <= 2; o <<= 1) {
      mx0 = fmaxf(mx0, __shfl_xor_sync(0xffffffffu, mx0, o));
      mx1 = fmaxf(mx1, __shfl_xor_sync(0xffffffffu, mx1, o));
    }
    const float mn0 = fmaxf(rowM0, mx0), mn1 = fmaxf(rowM1, mx1);
    const float fac0 = __expf(rowM0 - mn0), fac1 = __expf(rowM1 - mn1);
    rowM0 = mn0; rowM1 = mn1;
    float sum0 = 0.f, sum1 = 0.f;
#pragma unroll
    for (int nf = 0; nf < 8; nf++) {
      accS[nf][0] = __expf(accS[nf][0] - mn0);
      accS[nf][1] = __expf(accS[nf][1] - mn0);
      accS[nf][2] = __expf(accS[nf][2] - mn1);
      accS[nf][3] = __expf(accS[nf][3] - mn1);
      sum0 += accS[nf][0] + accS[nf][1];
      sum1 += accS[nf][2] + accS[nf][3];
    }
#pragma unroll
    for (int o = 1; o <= 2; o <<= 1) {
      sum0 += __shfl_xor_sync(0xffffffffu, sum0, o);
      sum1 += __shfl_xor_sync(0xffffffffu, sum1, o);
    }
    rowL0 = rowL0 * fac0 + sum0;
    rowL1 = rowL1 * fac1 + sum1;
#pragma unroll
    for (int nf = 0; nf < 8; nf++) {
      accO[nf][0] *= fac0; accO[nf][1] *= fac0;
      accO[nf][2] *= fac1; accO[nf][3] *= fac1;
    }

    // --- store P into A-frag layout (warp-private slices nf*8+w) ---
    const int f0 = ((2 * t) & 3) * 4 + ((2 * t) >> 2) * 2;       // col 2t
    const int f1 = ((2 * t + 1) & 3) * 4 + ((2 * t + 1) >> 2) * 2; // col 2t+1
#pragma unroll
    for (int nf = 0; nf < 8; nf++) {
      const int base = (nf * 8 + w) * 128 + g * 16;
      QPs[base + f0]     = f2tf32(accS[nf][0]);
      QPs[base + f1]     = f2tf32(accS[nf][1]);
      QPs[base + f0 + 1] = f2tf32(accS[nf][2]);
      QPs[base + f1 + 1] = f2tf32(accS[nf][3]);
    }
    __syncwarp();

    // --- O += P V : 8 kcP x 8 nf mma ---
#pragma unroll
    for (int kcP = 0; kcP < 8; kcP++) {
      uint32_t aP[4];
      const uint4 v = *(const uint4*)&QPs[(kcP * 8 + w) * 128 + lane * 4];
      aP[0] = v.x; aP[1] = v.y; aP[2] = v.z; aP[3] = v.w;
#pragma unroll
      for (int nf = 0; nf < 8; nf++) {
        uint32_t bf[2];
        const uint32_t* p = &Vs[(kcP * 8 + nf) * 64 + lane * 2];
        bf[0] = p[0]; bf[1] = p[1];
        mma_tf32(accO[nf], aP, bf);
      }
    }
    __syncwarp();   // P reads done before next iteration's P writes
  }

  // --- epilogue: normalize + write to g_att[B,N,C] ---
  const float inv0 = 1.f / rowL0, inv1 = 1.f / rowL1;
  const int row0 = q0 + w * 16 + g;
#pragma unroll
  for (int nf = 0; nf < 8; nf++) {
    const int col = h * 64 + nf * 8 + t * 2;
    float2 o0, o1;
    o0.x = accO[nf][0] * inv0; o0.y = accO[nf][1] * inv0;
    o1.x = accO[nf][2] * inv1; o1.y = accO[nf][3] * inv1;
    *(float2*)&g_att[(size_t)(b * N_ + row0) * C_ + col]     = o0;
    *(float2*)&g_att[(size_t)(b * N_ + row0 + 8) * C_ + col] = o1;
  }
}

extern "C" void kernel_launch(void* const* d_in, const int* in_sizes, int n_in,
                              void* d_out, int out_size) {
  const float* x      = (const float*)d_in[0];
  const int*   pad    = (const int*)  d_in[1];
  const float* w_attn = (const float*)d_in[2];
  const float* b_attn = (const float*)d_in[3];
  const float* w_proj = (const float*)d_in[4];
  const float* b_proj = (const float*)d_in[5];
  float* out = (float*)d_out;

  cudaFuncSetAttribute(attn_mma, cudaFuncAttributeMaxDynamicSharedMemorySize, 65536);

  // 1) QKV projection (mma.sync tf32) + bias + scatter to [B,H,N,D]
  mma_gemm<2304, true><<<dim3(18, 64), 256>>>(x, w_attn, b_attn, nullptr);
  // 2) fused attention (mma.sync tf32 flash attention)
  attn_mma<<<dim3(8, 96), 256, 65536>>>(pad);
  // 3) output projection (mma.sync tf32) + bias -> d_out
  mma_gemm<768, false><<<dim3(6, 64), 256>>>(nullptr, w_proj, b_proj, out);
}